// round 2
// baseline (speedup 1.0000x reference)
#include <cuda_runtime.h>
#include <math.h>

#define BB 8
#define CC 128
#define C2 256
#define NN 32768
#define KS 32
#define KCH (NN / KS)   // 1024 k-elements per energy split

// ---------------- scratch (static device globals; no allocations) ------------
__device__ float g_xcon[(size_t)BB * C2 * NN];   // [b][d][n]: d<128 = x_q, d>=128 = x_k   (256 MB)
__device__ float g_vcon[(size_t)BB * C2 * NN];   // [b][d][n]: d<128 = y_v, d>=128 = x_v   (256 MB)
__device__ float g_epart[(size_t)BB * KS * C2 * C2]; // split-K partials (64 MB)
__device__ float g_energy[BB * C2 * C2];
__device__ float g_e1[BB * C2 * C2];
__device__ float g_attn[BB * C2 * CC];           // attn[b][d][c]

// ---------------- kernel 1: four pointwise convs --------------------------
// grid (N/64, B, 4), block (16,16), dyn smem 96KB
extern "C" __global__ void __launch_bounds__(256, 2)
k_pconv(const float* __restrict__ x, const float* __restrict__ y,
        const float* __restrict__ qw, const float* __restrict__ qb,
        const float* __restrict__ kw, const float* __restrict__ kb,
        const float* __restrict__ v1w, const float* __restrict__ v1b,
        const float* __restrict__ v2w, const float* __restrict__ v2b)
{
    extern __shared__ float sm[];
    float* sWt = sm;             // [k=128][o=128]
    float* sX  = sm + 128 * 128; // [k=128][n=64]

    int b  = blockIdx.y;
    int n0 = blockIdx.x * 64;
    int z  = blockIdx.z;

    const float* W; const float* bias; const float* In; float* Out;
    if (z == 0)      { W = qw;  bias = qb;  In = y; Out = g_xcon + (size_t)b * C2 * NN; }
    else if (z == 1) { W = kw;  bias = kb;  In = x; Out = g_xcon + (size_t)b * C2 * NN + (size_t)CC * NN; }
    else if (z == 2) { W = v2w; bias = v2b; In = y; Out = g_vcon + (size_t)b * C2 * NN; }
    else             { W = v1w; bias = v1b; In = x; Out = g_vcon + (size_t)b * C2 * NN + (size_t)CC * NN; }
    In += (size_t)b * CC * NN;

    int tid = threadIdx.y * 16 + threadIdx.x;

    #pragma unroll 8
    for (int t = 0; t < 64; t++) {
        int idx = tid + t * 256;
        int o = idx >> 7, k = idx & 127;
        sWt[k * 128 + o] = W[idx];
    }
    #pragma unroll 8
    for (int t = 0; t < 32; t++) {
        int idx = tid + t * 256;
        int k = idx >> 6, c = idx & 63;
        sX[k * 64 + c] = In[(size_t)k * NN + n0 + c];
    }
    __syncthreads();

    int r0 = threadIdx.y * 8;
    int c0 = threadIdx.x * 4;
    float acc[8][4];
    #pragma unroll
    for (int i = 0; i < 8; i++)
        #pragma unroll
        for (int j = 0; j < 4; j++) acc[i][j] = 0.f;

    #pragma unroll 4
    for (int k = 0; k < 128; k++) {
        float wv[8], xv[4];
        #pragma unroll
        for (int i = 0; i < 8; i++) wv[i] = sWt[k * 128 + r0 + i];
        #pragma unroll
        for (int j = 0; j < 4; j++) xv[j] = sX[k * 64 + c0 + j];
        #pragma unroll
        for (int i = 0; i < 8; i++)
            #pragma unroll
            for (int j = 0; j < 4; j++)
                acc[i][j] += wv[i] * xv[j];
    }

    #pragma unroll
    for (int i = 0; i < 8; i++) {
        float bv = bias[r0 + i];
        #pragma unroll
        for (int j = 0; j < 4; j++)
            Out[(size_t)(r0 + i) * NN + n0 + c0 + j] = acc[i][j] + bv;
    }
}

// ---------------- kernel 2: energy split-K partials --------------------------
// grid (4 tiles, KS, B), block (16,16). 128x128 output tile, 8x8 micro.
extern "C" __global__ void __launch_bounds__(256, 1)
k_energy()
{
    __shared__ float sAt[32 * 129];
    __shared__ float sBt[32 * 129];

    int b   = blockIdx.z;
    int ksl = blockIdx.y;
    int i0  = (blockIdx.x >> 1) * 128;
    int j0  = (blockIdx.x & 1) * 128;
    const float* A = g_xcon + (size_t)b * C2 * NN;
    int tid = threadIdx.y * 16 + threadIdx.x;
    int k0  = ksl * KCH;

    float acc[8][8];
    #pragma unroll
    for (int i = 0; i < 8; i++)
        #pragma unroll
        for (int j = 0; j < 8; j++) acc[i][j] = 0.f;

    for (int kc = 0; kc < KCH; kc += 32) {
        __syncthreads();
        #pragma unroll 4
        for (int t = 0; t < 16; t++) {
            int e = tid + t * 256;
            int r = e >> 5, kk = e & 31;
            sAt[kk * 129 + r] = A[(size_t)(i0 + r) * NN + k0 + kc + kk];
            sBt[kk * 129 + r] = A[(size_t)(j0 + r) * NN + k0 + kc + kk];
        }
        __syncthreads();
        #pragma unroll
        for (int kk = 0; kk < 32; kk++) {
            float av[8], bv[8];
            #pragma unroll
            for (int q = 0; q < 4; q++) {
                av[q]     = sAt[kk * 129 + threadIdx.y * 4 + q];
                av[4 + q] = sAt[kk * 129 + 64 + threadIdx.y * 4 + q];
                bv[q]     = sBt[kk * 129 + threadIdx.x * 4 + q];
                bv[4 + q] = sBt[kk * 129 + 64 + threadIdx.x * 4 + q];
            }
            #pragma unroll
            for (int i = 0; i < 8; i++)
                #pragma unroll
                for (int j = 0; j < 8; j++)
                    acc[i][j] += av[i] * bv[j];
        }
    }

    float* Ep = g_epart + ((size_t)(b * KS + ksl) * C2) * C2;
    #pragma unroll
    for (int i = 0; i < 8; i++) {
        int ri = i0 + (i >> 2) * 64 + threadIdx.y * 4 + (i & 3);
        #pragma unroll
        for (int j = 0; j < 8; j++) {
            int cj = j0 + (j >> 2) * 64 + threadIdx.x * 4 + (j & 3);
            Ep[(size_t)ri * C2 + cj] = acc[i][j];
        }
    }
}

// ---------------- kernel 2b: deterministic split-K reduce + 1/sqrt(2C) ------
extern "C" __global__ void k_ereduce()
{
    int j = threadIdx.x, i = blockIdx.x, b = blockIdx.y;
    size_t base = ((size_t)b * KS * C2 + i) * C2 + j;
    float s = 0.f;
    #pragma unroll 8
    for (int ks = 0; ks < KS; ks++) s += g_epart[base + (size_t)ks * C2 * C2];
    g_energy[((size_t)b * C2 + i) * C2 + j] = s * (1.0f / 16.0f); // sqrt(256)=16
}

// ---------------- kernel 3a: e1 = relu(energy @ t1^T + t1_b) -----------------
// grid (16 rowgroups, B), block 256 (one thread per output col)
extern "C" __global__ void __launch_bounds__(256)
k_mlp1(const float* __restrict__ t1w, const float* __restrict__ t1b)
{
    __shared__ float sE[16 * 256];
    int b = blockIdx.y, rg = blockIdx.x;
    int tid = threadIdx.x;
    const float* E = g_energy + (size_t)b * C2 * C2 + (size_t)rg * 16 * C2;
    #pragma unroll
    for (int t = 0; t < 16; t++) sE[tid + t * 256] = E[tid + t * 256];
    __syncthreads();

    int j = tid;
    float acc[16];
    #pragma unroll
    for (int i = 0; i < 16; i++) acc[i] = 0.f;
    const float* wrow = t1w + (size_t)j * C2;
    for (int k = 0; k < 256; k++) {
        float w = wrow[k];
        #pragma unroll
        for (int i = 0; i < 16; i++) acc[i] += sE[i * 256 + k] * w;
    }
    float bv = t1b[j];
    float* O = g_e1 + (size_t)b * C2 * C2 + (size_t)rg * 16 * C2;
    #pragma unroll
    for (int i = 0; i < 16; i++) O[i * 256 + j] = fmaxf(acc[i] + bv, 0.f);
}

// ---------------- kernel 3b: e2 + softmax -> attn ---------------------------
// grid (256 rows, B), block 128
extern "C" __global__ void __launch_bounds__(128)
k_mlp2(const float* __restrict__ t2w, const float* __restrict__ t2b)
{
    __shared__ float sR[256];
    __shared__ float red[128];
    int b = blockIdx.y, i = blockIdx.x, j = threadIdx.x;
    const float* E1 = g_e1 + ((size_t)b * C2 + i) * C2;
    sR[j] = E1[j];
    sR[j + 128] = E1[j + 128];
    __syncthreads();

    const float* wrow = t2w + (size_t)j * C2;
    float d = 0.f;
    #pragma unroll 8
    for (int k = 0; k < 256; k++) d += sR[k] * wrow[k];
    float v = fmaxf(d + t2b[j], 0.f);

    red[j] = v; __syncthreads();
    for (int s = 64; s > 0; s >>= 1) {
        if (j < s) red[j] = fmaxf(red[j], red[j + s]);
        __syncthreads();
    }
    float m = red[0]; __syncthreads();
    float e = expf(v - m);
    red[j] = e; __syncthreads();
    for (int s = 64; s > 0; s >>= 1) {
        if (j < s) red[j] += red[j + s];
        __syncthreads();
    }
    float sum = red[0];
    g_attn[((size_t)b * C2 + i) * CC + j] = e / sum;
}

// ---------------- kernel 4: out = attn^T @ vcon ------------------------------
// grid (N/64, B), block (16,16), dyn smem ~144KB
extern "C" __global__ void __launch_bounds__(256, 1)
k_out(float* __restrict__ out)
{
    extern __shared__ float sm[];
    float* sAttn = sm;             // [d=256][c=128]
    float* sV    = sm + 256 * 128; // [kk=64][n=64] pad 65

    int b = blockIdx.y;
    int n0 = blockIdx.x * 64;
    int tid = threadIdx.y * 16 + threadIdx.x;

    const float* At = g_attn + (size_t)b * C2 * CC;
    for (int t = 0; t < 128; t++) sAttn[tid + t * 256] = At[tid + t * 256];

    const float* V = g_vcon + (size_t)b * C2 * NN;
    int c0r = threadIdx.y * 8;  // output channel
    int nl0 = threadIdx.x * 4;  // n within tile
    float acc[8][4];
    #pragma unroll
    for (int i = 0; i < 8; i++)
        #pragma unroll
        for (int j = 0; j < 4; j++) acc[i][j] = 0.f;

    for (int dd = 0; dd < 4; dd++) {
        __syncthreads();
        #pragma unroll 4
        for (int t = 0; t < 16; t++) {
            int e = tid + t * 256;
            int kk = e >> 6, c = e & 63;
            sV[kk * 65 + c] = V[(size_t)(dd * 64 + kk) * NN + n0 + c];
        }
        __syncthreads();
        #pragma unroll 4
        for (int kk = 0; kk < 64; kk++) {
            int d = dd * 64 + kk;
            float a[8], vv[4];
            #pragma unroll
            for (int i = 0; i < 8; i++) a[i] = sAttn[d * 128 + c0r + i];
            #pragma unroll
            for (int j = 0; j < 4; j++) vv[j] = sV[kk * 65 + nl0 + j];
            #pragma unroll
            for (int i = 0; i < 8; i++)
                #pragma unroll
                for (int j = 0; j < 4; j++)
                    acc[i][j] += a[i] * vv[j];
        }
    }

    #pragma unroll
    for (int i = 0; i < 8; i++)
        #pragma unroll
        for (int j = 0; j < 4; j++)
            out[((size_t)b * CC + c0r + i) * NN + n0 + nl0 + j] = acc[i][j];
}

// ---------------- launch -----------------------------------------------------
extern "C" void kernel_launch(void* const* d_in, const int* in_sizes, int n_in,
                              void* d_out, int out_size)
{
    const float* x   = (const float*)d_in[0];
    const float* y   = (const float*)d_in[1];
    const float* qw  = (const float*)d_in[2];
    const float* qb  = (const float*)d_in[3];
    const float* kw  = (const float*)d_in[4];
    const float* kb  = (const float*)d_in[5];
    const float* v1w = (const float*)d_in[6];
    const float* v1b = (const float*)d_in[7];
    const float* v2w = (const float*)d_in[8];
    const float* v2b = (const float*)d_in[9];
    const float* t1w = (const float*)d_in[10];
    const float* t1b = (const float*)d_in[11];
    const float* t2w = (const float*)d_in[12];
    const float* t2b = (const float*)d_in[13];
    float* out = (float*)d_out;

    cudaFuncSetAttribute(k_pconv, cudaFuncAttributeMaxDynamicSharedMemorySize, 98304);
    cudaFuncSetAttribute(k_out,   cudaFuncAttributeMaxDynamicSharedMemorySize, 147712);

    dim3 b16(16, 16);
    k_pconv <<<dim3(NN / 64, BB, 4), b16, 98304>>>(x, y, qw, qb, kw, kb, v1w, v1b, v2w, v2b);
    k_energy<<<dim3(4, KS, BB), b16>>>();
    k_ereduce<<<dim3(C2, BB), C2>>>();
    k_mlp1  <<<dim3(16, BB), 256>>>(t1w, t1b);
    k_mlp2  <<<dim3(C2, BB), CC>>>(t2w, t2b);
    k_out   <<<dim3(NN / 64, BB), b16, 147712>>>(out);
}

// round 3
// speedup vs baseline: 1.0512x; 1.0512x over previous
#include <cuda_runtime.h>
#include <math.h>

#define BB 8
#define CC 128
#define C2 256
#define NN 32768
#define KS 32
#define KCH (NN / KS)   // 1024 k-elements per energy split

// ---------------- scratch (static device globals; no allocations) ------------
__device__ float g_xcon[(size_t)BB * C2 * NN];   // [b][d][n]: d<128 = x_q, d>=128 = x_k   (256 MB)
__device__ float g_vcon[(size_t)BB * C2 * NN];   // [b][d][n]: d<128 = y_v, d>=128 = x_v   (256 MB)
__device__ float g_epart[(size_t)BB * KS * C2 * C2]; // split-K partials (64 MB)
__device__ float g_energy[BB * C2 * C2];
__device__ float g_e1[BB * C2 * C2];
__device__ float g_attn[BB * C2 * CC];           // attn[b][d][c]

// ---------------- kernel 1: four pointwise convs --------------------------
// grid (N/64, B, 4), block (16,16), dyn smem 96KB
extern "C" __global__ void __launch_bounds__(256, 2)
k_pconv(const float* __restrict__ x, const float* __restrict__ y,
        const float* __restrict__ qw, const float* __restrict__ qb,
        const float* __restrict__ kw, const float* __restrict__ kb,
        const float* __restrict__ v1w, const float* __restrict__ v1b,
        const float* __restrict__ v2w, const float* __restrict__ v2b)
{
    extern __shared__ float sm[];
    float* sWt = sm;             // [k=128][o=128]
    float* sX  = sm + 128 * 128; // [k=128][n=64]

    int b  = blockIdx.y;
    int n0 = blockIdx.x * 64;
    int z  = blockIdx.z;

    const float* W; const float* bias; const float* In; float* Out;
    if (z == 0)      { W = qw;  bias = qb;  In = y; Out = g_xcon + (size_t)b * C2 * NN; }
    else if (z == 1) { W = kw;  bias = kb;  In = x; Out = g_xcon + (size_t)b * C2 * NN + (size_t)CC * NN; }
    else if (z == 2) { W = v2w; bias = v2b; In = y; Out = g_vcon + (size_t)b * C2 * NN; }
    else             { W = v1w; bias = v1b; In = x; Out = g_vcon + (size_t)b * C2 * NN + (size_t)CC * NN; }
    In += (size_t)b * CC * NN;

    int tid = threadIdx.y * 16 + threadIdx.x;

    #pragma unroll 8
    for (int t = 0; t < 64; t++) {
        int idx = tid + t * 256;
        int o = idx >> 7, k = idx & 127;
        sWt[k * 128 + o] = W[idx];
    }
    #pragma unroll 8
    for (int t = 0; t < 32; t++) {
        int idx = tid + t * 256;
        int k = idx >> 6, c = idx & 63;
        sX[k * 64 + c] = In[(size_t)k * NN + n0 + c];
    }
    __syncthreads();

    int r0 = threadIdx.y * 8;
    int c0 = threadIdx.x * 4;
    float acc[8][4];
    #pragma unroll
    for (int i = 0; i < 8; i++)
        #pragma unroll
        for (int j = 0; j < 4; j++) acc[i][j] = 0.f;

    #pragma unroll 4
    for (int k = 0; k < 128; k++) {
        float wv[8], xv[4];
        #pragma unroll
        for (int i = 0; i < 8; i++) wv[i] = sWt[k * 128 + r0 + i];
        #pragma unroll
        for (int j = 0; j < 4; j++) xv[j] = sX[k * 64 + c0 + j];
        #pragma unroll
        for (int i = 0; i < 8; i++)
            #pragma unroll
            for (int j = 0; j < 4; j++)
                acc[i][j] += wv[i] * xv[j];
    }

    #pragma unroll
    for (int i = 0; i < 8; i++) {
        float bv = bias[r0 + i];
        #pragma unroll
        for (int j = 0; j < 4; j++)
            Out[(size_t)(r0 + i) * NN + n0 + c0 + j] = acc[i][j] + bv;
    }
}

// ---------------- kernel 2: energy split-K partials --------------------------
// grid (4 tiles, KS, B), block (16,16). 128x128 output tile, 8x8 micro.
extern "C" __global__ void __launch_bounds__(256, 1)
k_energy()
{
    __shared__ float sAt[32 * 129];
    __shared__ float sBt[32 * 129];

    int b   = blockIdx.z;
    int ksl = blockIdx.y;
    int i0  = (blockIdx.x >> 1) * 128;
    int j0  = (blockIdx.x & 1) * 128;
    const float* A = g_xcon + (size_t)b * C2 * NN;
    int tid = threadIdx.y * 16 + threadIdx.x;
    int k0  = ksl * KCH;

    float acc[8][8];
    #pragma unroll
    for (int i = 0; i < 8; i++)
        #pragma unroll
        for (int j = 0; j < 8; j++) acc[i][j] = 0.f;

    for (int kc = 0; kc < KCH; kc += 32) {
        __syncthreads();
        #pragma unroll 4
        for (int t = 0; t < 16; t++) {
            int e = tid + t * 256;
            int r = e >> 5, kk = e & 31;
            sAt[kk * 129 + r] = A[(size_t)(i0 + r) * NN + k0 + kc + kk];
            sBt[kk * 129 + r] = A[(size_t)(j0 + r) * NN + k0 + kc + kk];
        }
        __syncthreads();
        #pragma unroll
        for (int kk = 0; kk < 32; kk++) {
            float av[8], bv[8];
            #pragma unroll
            for (int q = 0; q < 4; q++) {
                av[q]     = sAt[kk * 129 + threadIdx.y * 4 + q];
                av[4 + q] = sAt[kk * 129 + 64 + threadIdx.y * 4 + q];
                bv[q]     = sBt[kk * 129 + threadIdx.x * 4 + q];
                bv[4 + q] = sBt[kk * 129 + 64 + threadIdx.x * 4 + q];
            }
            #pragma unroll
            for (int i = 0; i < 8; i++)
                #pragma unroll
                for (int j = 0; j < 8; j++)
                    acc[i][j] += av[i] * bv[j];
        }
    }

    float* Ep = g_epart + ((size_t)(b * KS + ksl) * C2) * C2;
    #pragma unroll
    for (int i = 0; i < 8; i++) {
        int ri = i0 + (i >> 2) * 64 + threadIdx.y * 4 + (i & 3);
        #pragma unroll
        for (int j = 0; j < 8; j++) {
            int cj = j0 + (j >> 2) * 64 + threadIdx.x * 4 + (j & 3);
            Ep[(size_t)ri * C2 + cj] = acc[i][j];
        }
    }
}

// ---------------- kernel 2b: deterministic split-K reduce + 1/sqrt(2C) ------
extern "C" __global__ void k_ereduce()
{
    int j = threadIdx.x, i = blockIdx.x, b = blockIdx.y;
    size_t base = ((size_t)b * KS * C2 + i) * C2 + j;
    float s = 0.f;
    #pragma unroll 8
    for (int ks = 0; ks < KS; ks++) s += g_epart[base + (size_t)ks * C2 * C2];
    g_energy[((size_t)b * C2 + i) * C2 + j] = s * (1.0f / 16.0f); // sqrt(256)=16
}

// ---------------- kernel 3a: e1 = relu(energy @ t1^T + t1_b) -----------------
// grid (16 rowgroups, B), block 256 (one thread per output col)
extern "C" __global__ void __launch_bounds__(256)
k_mlp1(const float* __restrict__ t1w, const float* __restrict__ t1b)
{
    __shared__ float sE[16 * 256];
    int b = blockIdx.y, rg = blockIdx.x;
    int tid = threadIdx.x;
    const float* E = g_energy + (size_t)b * C2 * C2 + (size_t)rg * 16 * C2;
    #pragma unroll
    for (int t = 0; t < 16; t++) sE[tid + t * 256] = E[tid + t * 256];
    __syncthreads();

    int j = tid;
    float acc[16];
    #pragma unroll
    for (int i = 0; i < 16; i++) acc[i] = 0.f;
    const float* wrow = t1w + (size_t)j * C2;
    for (int k = 0; k < 256; k++) {
        float w = wrow[k];
        #pragma unroll
        for (int i = 0; i < 16; i++) acc[i] += sE[i * 256 + k] * w;
    }
    float bv = t1b[j];
    float* O = g_e1 + (size_t)b * C2 * C2 + (size_t)rg * 16 * C2;
    #pragma unroll
    for (int i = 0; i < 16; i++) O[i * 256 + j] = fmaxf(acc[i] + bv, 0.f);
}

// ---------------- kernel 3b: e2 + softmax -> attn ---------------------------
// grid (256 rows, B), block 128
extern "C" __global__ void __launch_bounds__(128)
k_mlp2(const float* __restrict__ t2w, const float* __restrict__ t2b)
{
    __shared__ float sR[256];
    __shared__ float red[128];
    int b = blockIdx.y, i = blockIdx.x, j = threadIdx.x;
    const float* E1 = g_e1 + ((size_t)b * C2 + i) * C2;
    sR[j] = E1[j];
    sR[j + 128] = E1[j + 128];
    __syncthreads();

    const float* wrow = t2w + (size_t)j * C2;
    float d = 0.f;
    #pragma unroll 8
    for (int k = 0; k < 256; k++) d += sR[k] * wrow[k];
    float v = fmaxf(d + t2b[j], 0.f);

    red[j] = v; __syncthreads();
    for (int s = 64; s > 0; s >>= 1) {
        if (j < s) red[j] = fmaxf(red[j], red[j + s]);
        __syncthreads();
    }
    float m = red[0]; __syncthreads();
    float e = expf(v - m);
    red[j] = e; __syncthreads();
    for (int s = 64; s > 0; s >>= 1) {
        if (j < s) red[j] += red[j + s];
        __syncthreads();
    }
    float sum = red[0];
    g_attn[((size_t)b * C2 + i) * CC + j] = e / sum;
}

// ---------------- kernel 4: out = attn^T @ vcon ------------------------------
// grid (N/64, B), block (16,16), dyn smem ~144KB
extern "C" __global__ void __launch_bounds__(256, 1)
k_out(float* __restrict__ out)
{
    extern __shared__ float sm[];
    float* sAttn = sm;             // [d=256][c=128]
    float* sV    = sm + 256 * 128; // [kk=64][n=64] pad 65

    int b = blockIdx.y;
    int n0 = blockIdx.x * 64;
    int tid = threadIdx.y * 16 + threadIdx.x;

    const float* At = g_attn + (size_t)b * C2 * CC;
    for (int t = 0; t < 128; t++) sAttn[tid + t * 256] = At[tid + t * 256];

    const float* V = g_vcon + (size_t)b * C2 * NN;
    int c0r = threadIdx.y * 8;  // output channel
    int nl0 = threadIdx.x * 4;  // n within tile
    float acc[8][4];
    #pragma unroll
    for (int i = 0; i < 8; i++)
        #pragma unroll
        for (int j = 0; j < 4; j++) acc[i][j] = 0.f;

    for (int dd = 0; dd < 4; dd++) {
        __syncthreads();
        #pragma unroll 4
        for (int t = 0; t < 16; t++) {
            int e = tid + t * 256;
            int kk = e >> 6, c = e & 63;
            sV[kk * 65 + c] = V[(size_t)(dd * 64 + kk) * NN + n0 + c];
        }
        __syncthreads();
        #pragma unroll 4
        for (int kk = 0; kk < 64; kk++) {
            int d = dd * 64 + kk;
            float a[8], vv[4];
            #pragma unroll
            for (int i = 0; i < 8; i++) a[i] = sAttn[d * 128 + c0r + i];
            #pragma unroll
            for (int j = 0; j < 4; j++) vv[j] = sV[kk * 65 + nl0 + j];
            #pragma unroll
            for (int i = 0; i < 8; i++)
                #pragma unroll
                for (int j = 0; j < 4; j++)
                    acc[i][j] += a[i] * vv[j];
        }
    }

    #pragma unroll
    for (int i = 0; i < 8; i++)
        #pragma unroll
        for (int j = 0; j < 4; j++)
            out[((size_t)b * CC + c0r + i) * NN + n0 + nl0 + j] = acc[i][j];
}

// ---------------- launch -----------------------------------------------------
extern "C" void kernel_launch(void* const* d_in, const int* in_sizes, int n_in,
                              void* d_out, int out_size)
{
    const float* x   = (const float*)d_in[0];
    const float* y   = (const float*)d_in[1];
    const float* qw  = (const float*)d_in[2];
    const float* qb  = (const float*)d_in[3];
    const float* kw  = (const float*)d_in[4];
    const float* kb  = (const float*)d_in[5];
    const float* v1w = (const float*)d_in[6];
    const float* v1b = (const float*)d_in[7];
    const float* v2w = (const float*)d_in[8];
    const float* v2b = (const float*)d_in[9];
    const float* t1w = (const float*)d_in[10];
    const float* t1b = (const float*)d_in[11];
    const float* t2w = (const float*)d_in[12];
    const float* t2b = (const float*)d_in[13];
    float* out = (float*)d_out;

    cudaFuncSetAttribute(k_pconv, cudaFuncAttributeMaxDynamicSharedMemorySize, 98304);
    cudaFuncSetAttribute(k_out,   cudaFuncAttributeMaxDynamicSharedMemorySize, 147712);

    dim3 b16(16, 16);
    k_pconv <<<dim3(NN / 64, BB, 4), b16, 98304>>>(x, y, qw, qb, kw, kb, v1w, v1b, v2w, v2b);
    k_energy<<<dim3(4, KS, BB), b16>>>();
    k_ereduce<<<dim3(C2, BB), C2>>>();
    k_mlp1  <<<dim3(16, BB), 256>>>(t1w, t1b);
    k_mlp2  <<<dim3(C2, BB), CC>>>(t2w, t2b);
    k_out   <<<dim3(NN / 64, BB), b16, 147712>>>(out);
}

// round 4
// speedup vs baseline: 1.0516x; 1.0004x over previous
#include <cuda_runtime.h>
#include <math.h>

#define BB 8
#define CC 128
#define C2 256
#define NN 32768
#define KS 32
#define KCH (NN / KS)   // 1024 k-elements per energy split

// ---------------- scratch (static device globals; no allocations) ------------
__device__ float g_xcon[(size_t)BB * C2 * NN];   // [b][d][n]: d<128 = x_q, d>=128 = x_k   (256 MB)
__device__ float g_vcon[(size_t)BB * C2 * NN];   // [b][d][n]: d<128 = y_v, d>=128 = x_v   (256 MB)
__device__ float g_epart[(size_t)BB * KS * C2 * C2]; // split-K partials (64 MB)
__device__ float g_energy[BB * C2 * C2];
__device__ float g_e1[BB * C2 * C2];
__device__ float g_attn[BB * C2 * CC];           // attn[b][d][c]

// ---------------- kernel 1: four pointwise convs --------------------------
// grid (N/64, B, 4), block (16,16), dyn smem 96KB
extern "C" __global__ void __launch_bounds__(256, 2)
k_pconv(const float* __restrict__ x, const float* __restrict__ y,
        const float* __restrict__ qw, const float* __restrict__ qb,
        const float* __restrict__ kw, const float* __restrict__ kb,
        const float* __restrict__ v1w, const float* __restrict__ v1b,
        const float* __restrict__ v2w, const float* __restrict__ v2b)
{
    extern __shared__ float sm[];
    float* sWt = sm;             // [k=128][o=128]
    float* sX  = sm + 128 * 128; // [k=128][n=64]

    int b  = blockIdx.y;
    int n0 = blockIdx.x * 64;
    int z  = blockIdx.z;

    const float* W; const float* bias; const float* In; float* Out;
    if (z == 0)      { W = qw;  bias = qb;  In = y; Out = g_xcon + (size_t)b * C2 * NN; }
    else if (z == 1) { W = kw;  bias = kb;  In = x; Out = g_xcon + (size_t)b * C2 * NN + (size_t)CC * NN; }
    else if (z == 2) { W = v2w; bias = v2b; In = y; Out = g_vcon + (size_t)b * C2 * NN; }
    else             { W = v1w; bias = v1b; In = x; Out = g_vcon + (size_t)b * C2 * NN + (size_t)CC * NN; }
    In += (size_t)b * CC * NN;

    int tid = threadIdx.y * 16 + threadIdx.x;

    #pragma unroll 8
    for (int t = 0; t < 64; t++) {
        int idx = tid + t * 256;
        int o = idx >> 7, k = idx & 127;
        sWt[k * 128 + o] = W[idx];
    }
    #pragma unroll 8
    for (int t = 0; t < 32; t++) {
        int idx = tid + t * 256;
        int k = idx >> 6, c = idx & 63;
        sX[k * 64 + c] = In[(size_t)k * NN + n0 + c];
    }
    __syncthreads();

    int r0 = threadIdx.y * 8;
    int c0 = threadIdx.x * 4;
    float acc[8][4];
    #pragma unroll
    for (int i = 0; i < 8; i++)
        #pragma unroll
        for (int j = 0; j < 4; j++) acc[i][j] = 0.f;

    #pragma unroll 4
    for (int k = 0; k < 128; k++) {
        float wv[8], xv[4];
        #pragma unroll
        for (int i = 0; i < 8; i++) wv[i] = sWt[k * 128 + r0 + i];
        #pragma unroll
        for (int j = 0; j < 4; j++) xv[j] = sX[k * 64 + c0 + j];
        #pragma unroll
        for (int i = 0; i < 8; i++)
            #pragma unroll
            for (int j = 0; j < 4; j++)
                acc[i][j] += wv[i] * xv[j];
    }

    #pragma unroll
    for (int i = 0; i < 8; i++) {
        float bv = bias[r0 + i];
        #pragma unroll
        for (int j = 0; j < 4; j++)
            Out[(size_t)(r0 + i) * NN + n0 + c0 + j] = acc[i][j] + bv;
    }
}

// ---------------- kernel 2: energy split-K partials --------------------------
// grid (4 tiles, KS, B), block (16,16). 128x128 output tile, 8x8 micro.
extern "C" __global__ void __launch_bounds__(256, 1)
k_energy()
{
    __shared__ float sAt[32 * 129];
    __shared__ float sBt[32 * 129];

    int b   = blockIdx.z;
    int ksl = blockIdx.y;
    int i0  = (blockIdx.x >> 1) * 128;
    int j0  = (blockIdx.x & 1) * 128;
    const float* A = g_xcon + (size_t)b * C2 * NN;
    int tid = threadIdx.y * 16 + threadIdx.x;
    int k0  = ksl * KCH;

    float acc[8][8];
    #pragma unroll
    for (int i = 0; i < 8; i++)
        #pragma unroll
        for (int j = 0; j < 8; j++) acc[i][j] = 0.f;

    for (int kc = 0; kc < KCH; kc += 32) {
        __syncthreads();
        #pragma unroll 4
        for (int t = 0; t < 16; t++) {
            int e = tid + t * 256;
            int r = e >> 5, kk = e & 31;
            sAt[kk * 129 + r] = A[(size_t)(i0 + r) * NN + k0 + kc + kk];
            sBt[kk * 129 + r] = A[(size_t)(j0 + r) * NN + k0 + kc + kk];
        }
        __syncthreads();
        #pragma unroll
        for (int kk = 0; kk < 32; kk++) {
            float av[8], bv[8];
            #pragma unroll
            for (int q = 0; q < 4; q++) {
                av[q]     = sAt[kk * 129 + threadIdx.y * 4 + q];
                av[4 + q] = sAt[kk * 129 + 64 + threadIdx.y * 4 + q];
                bv[q]     = sBt[kk * 129 + threadIdx.x * 4 + q];
                bv[4 + q] = sBt[kk * 129 + 64 + threadIdx.x * 4 + q];
            }
            #pragma unroll
            for (int i = 0; i < 8; i++)
                #pragma unroll
                for (int j = 0; j < 8; j++)
                    acc[i][j] += av[i] * bv[j];
        }
    }

    float* Ep = g_epart + ((size_t)(b * KS + ksl) * C2) * C2;
    #pragma unroll
    for (int i = 0; i < 8; i++) {
        int ri = i0 + (i >> 2) * 64 + threadIdx.y * 4 + (i & 3);
        #pragma unroll
        for (int j = 0; j < 8; j++) {
            int cj = j0 + (j >> 2) * 64 + threadIdx.x * 4 + (j & 3);
            Ep[(size_t)ri * C2 + cj] = acc[i][j];
        }
    }
}

// ---------------- kernel 2b: deterministic split-K reduce + 1/sqrt(2C) ------
extern "C" __global__ void k_ereduce()
{
    int j = threadIdx.x, i = blockIdx.x, b = blockIdx.y;
    size_t base = ((size_t)b * KS * C2 + i) * C2 + j;
    float s = 0.f;
    #pragma unroll 8
    for (int ks = 0; ks < KS; ks++) s += g_epart[base + (size_t)ks * C2 * C2];
    g_energy[((size_t)b * C2 + i) * C2 + j] = s * (1.0f / 16.0f); // sqrt(256)=16
}

// ---------------- kernel 3a: e1 = relu(energy @ t1^T + t1_b) -----------------
// grid (16 rowgroups, B), block 256 (one thread per output col)
extern "C" __global__ void __launch_bounds__(256)
k_mlp1(const float* __restrict__ t1w, const float* __restrict__ t1b)
{
    __shared__ float sE[16 * 256];
    int b = blockIdx.y, rg = blockIdx.x;
    int tid = threadIdx.x;
    const float* E = g_energy + (size_t)b * C2 * C2 + (size_t)rg * 16 * C2;
    #pragma unroll
    for (int t = 0; t < 16; t++) sE[tid + t * 256] = E[tid + t * 256];
    __syncthreads();

    int j = tid;
    float acc[16];
    #pragma unroll
    for (int i = 0; i < 16; i++) acc[i] = 0.f;
    const float* wrow = t1w + (size_t)j * C2;
    for (int k = 0; k < 256; k++) {
        float w = wrow[k];
        #pragma unroll
        for (int i = 0; i < 16; i++) acc[i] += sE[i * 256 + k] * w;
    }
    float bv = t1b[j];
    float* O = g_e1 + (size_t)b * C2 * C2 + (size_t)rg * 16 * C2;
    #pragma unroll
    for (int i = 0; i < 16; i++) O[i * 256 + j] = fmaxf(acc[i] + bv, 0.f);
}

// ---------------- kernel 3b: e2 + softmax -> attn ---------------------------
// grid (256 rows, B), block 128
extern "C" __global__ void __launch_bounds__(128)
k_mlp2(const float* __restrict__ t2w, const float* __restrict__ t2b)
{
    __shared__ float sR[256];
    __shared__ float red[128];
    int b = blockIdx.y, i = blockIdx.x, j = threadIdx.x;
    const float* E1 = g_e1 + ((size_t)b * C2 + i) * C2;
    sR[j] = E1[j];
    sR[j + 128] = E1[j + 128];
    __syncthreads();

    const float* wrow = t2w + (size_t)j * C2;
    float d = 0.f;
    #pragma unroll 8
    for (int k = 0; k < 256; k++) d += sR[k] * wrow[k];
    float v = fmaxf(d + t2b[j], 0.f);

    red[j] = v; __syncthreads();
    for (int s = 64; s > 0; s >>= 1) {
        if (j < s) red[j] = fmaxf(red[j], red[j + s]);
        __syncthreads();
    }
    float m = red[0]; __syncthreads();
    float e = expf(v - m);
    red[j] = e; __syncthreads();
    for (int s = 64; s > 0; s >>= 1) {
        if (j < s) red[j] += red[j + s];
        __syncthreads();
    }
    float sum = red[0];
    g_attn[((size_t)b * C2 + i) * CC + j] = e / sum;
}

// ---------------- kernel 4: out = attn^T @ vcon ------------------------------
// grid (N/64, B), block (16,16), dyn smem ~144KB
extern "C" __global__ void __launch_bounds__(256, 1)
k_out(float* __restrict__ out)
{
    extern __shared__ float sm[];
    float* sAttn = sm;             // [d=256][c=128]
    float* sV    = sm + 256 * 128; // [kk=64][n=64] pad 65

    int b = blockIdx.y;
    int n0 = blockIdx.x * 64;
    int tid = threadIdx.y * 16 + threadIdx.x;

    const float* At = g_attn + (size_t)b * C2 * CC;
    for (int t = 0; t < 128; t++) sAttn[tid + t * 256] = At[tid + t * 256];

    const float* V = g_vcon + (size_t)b * C2 * NN;
    int c0r = threadIdx.y * 8;  // output channel
    int nl0 = threadIdx.x * 4;  // n within tile
    float acc[8][4];
    #pragma unroll
    for (int i = 0; i < 8; i++)
        #pragma unroll
        for (int j = 0; j < 4; j++) acc[i][j] = 0.f;

    for (int dd = 0; dd < 4; dd++) {
        __syncthreads();
        #pragma unroll 4
        for (int t = 0; t < 16; t++) {
            int e = tid + t * 256;
            int kk = e >> 6, c = e & 63;
            sV[kk * 65 + c] = V[(size_t)(dd * 64 + kk) * NN + n0 + c];
        }
        __syncthreads();
        #pragma unroll 4
        for (int kk = 0; kk < 64; kk++) {
            int d = dd * 64 + kk;
            float a[8], vv[4];
            #pragma unroll
            for (int i = 0; i < 8; i++) a[i] = sAttn[d * 128 + c0r + i];
            #pragma unroll
            for (int j = 0; j < 4; j++) vv[j] = sV[kk * 65 + nl0 + j];
            #pragma unroll
            for (int i = 0; i < 8; i++)
                #pragma unroll
                for (int j = 0; j < 4; j++)
                    acc[i][j] += a[i] * vv[j];
        }
    }

    #pragma unroll
    for (int i = 0; i < 8; i++)
        #pragma unroll
        for (int j = 0; j < 4; j++)
            out[((size_t)b * CC + c0r + i) * NN + n0 + nl0 + j] = acc[i][j];
}

// ---------------- launch -----------------------------------------------------
extern "C" void kernel_launch(void* const* d_in, const int* in_sizes, int n_in,
                              void* d_out, int out_size)
{
    const float* x   = (const float*)d_in[0];
    const float* y   = (const float*)d_in[1];
    const float* qw  = (const float*)d_in[2];
    const float* qb  = (const float*)d_in[3];
    const float* kw  = (const float*)d_in[4];
    const float* kb  = (const float*)d_in[5];
    const float* v1w = (const float*)d_in[6];
    const float* v1b = (const float*)d_in[7];
    const float* v2w = (const float*)d_in[8];
    const float* v2b = (const float*)d_in[9];
    const float* t1w = (const float*)d_in[10];
    const float* t1b = (const float*)d_in[11];
    const float* t2w = (const float*)d_in[12];
    const float* t2b = (const float*)d_in[13];
    float* out = (float*)d_out;

    cudaFuncSetAttribute(k_pconv, cudaFuncAttributeMaxDynamicSharedMemorySize, 98304);
    cudaFuncSetAttribute(k_out,   cudaFuncAttributeMaxDynamicSharedMemorySize, 147712);

    dim3 b16(16, 16);
    k_pconv <<<dim3(NN / 64, BB, 4), b16, 98304>>>(x, y, qw, qb, kw, kb, v1w, v1b, v2w, v2b);
    k_energy<<<dim3(4, KS, BB), b16>>>();
    k_ereduce<<<dim3(C2, BB), C2>>>();
    k_mlp1  <<<dim3(16, BB), 256>>>(t1w, t1b);
    k_mlp2  <<<dim3(C2, BB), CC>>>(t2w, t2b);
    k_out   <<<dim3(NN / 64, BB), b16, 147712>>>(out);
}